// round 3
// baseline (speedup 1.0000x reference)
#include <cuda_runtime.h>

#define KK 48
#define TT 1024
#define BB 512
#define NEG_BIG (-3.0e38f)
#define KBIG (1 << 28)

// ---------------- device scratch ----------------
// Epacked[l*48+i] = (E[i][l], l<16 ? E[i][l+32] : 0), E = exp(trans) or 0 if forbidden
__device__ float2 d_Epacked[32 * KK];
__device__ double d_ztmp[2 * BB];
__device__ int    d_mode;   // 1 = bools are 1 byte, 0 = bools are 4-byte words

// ---------------- f32x2 helpers ----------------
__device__ __forceinline__ unsigned long long ffma2(unsigned long long a,
                                                    unsigned long long b,
                                                    unsigned long long c) {
    unsigned long long d;
    asm("fma.rn.f32x2 %0, %1, %2, %3;" : "=l"(d) : "l"(a), "l"(b), "l"(c));
    return d;
}
__device__ __forceinline__ unsigned long long fadd2(unsigned long long a,
                                                    unsigned long long b) {
    unsigned long long d;
    asm("add.rn.f32x2 %0, %1, %2;" : "=l"(d) : "l"(a), "l"(b));
    return d;
}
__device__ __forceinline__ unsigned long long dup2(float x) {
    unsigned long long d;
    asm("mov.b64 %0, {%1, %1};" : "=l"(d) : "f"(x));
    return d;
}
__device__ __forceinline__ void unpack2(unsigned long long v, float& lo, float& hi) {
    asm("mov.b64 {%0, %1}, %2;" : "=f"(lo), "=f"(hi) : "l"(v));
}

// ---------------- kernel 0: detect bool dump width ----------------
__global__ void detect_kernel(const unsigned int* __restrict__ mask_words) {
    if (threadIdx.x == 0) {
        // mask[0..3] are all true (lengths >= 512). Bytes -> 0x01010101.
        // int32 -> 0x00000001, float32 -> 0x3F800000.
        d_mode = (mask_words[0] == 0x01010101u) ? 1 : 0;
    }
}

// ---------------- kernel 1: precompute exp(transitions) ----------------
__global__ void precompute_kernel(const float* __restrict__ trans,
                                  const void* __restrict__ forb) {
    const int mode = d_mode;
    const unsigned char* f8 = (const unsigned char*)forb;
    const unsigned int* f32v = (const unsigned int*)forb;
    int idx = blockIdx.x * blockDim.x + threadIdx.x;
    int stride = gridDim.x * blockDim.x;
    for (int x = idx; x < 32 * KK; x += stride) {
        int l = x / KK;
        int i = x % KK;
        bool fb_lo = mode ? (f8[i * KK + l] != 0) : (f32v[i * KK + l] != 0u);
        float ex = fb_lo ? 0.0f : __expf(trans[i * KK + l]);
        float ey = 0.0f;
        if (l < 16) {
            bool fb_hi = mode ? (f8[i * KK + l + 32] != 0) : (f32v[i * KK + l + 32] != 0u);
            ey = fb_hi ? 0.0f : __expf(trans[i * KK + l + 32]);
        }
        d_Epacked[x] = make_float2(ex, ey);
    }
}

// ---------------- kernel 2: forward recurrence with tier tracking ----------------
// MODE: 1 = bool inputs are bytes, 0 = bool inputs are 4-byte words.
template <int MODE>
__global__ void __launch_bounds__(32) crf_forward_kernel(
    const float* __restrict__ emissions,
    const void* __restrict__ maskv,
    const void* __restrict__ targetv,
    const float* __restrict__ startp,
    const void* __restrict__ sforbv,
    const float* __restrict__ endp,
    const void* __restrict__ eforbv) {
    if (d_mode != MODE) return;   // the other instantiation handles this data

    __shared__ __align__(16) float psm0[2][64];
    __shared__ __align__(16) float psm1[2][64];

    const int lane = threadIdx.x & 31;
    const int chain = blockIdx.x;          // 0..1023
    const int b = chain >> 1;
    const bool sup = (chain & 1) == 0;     // channel 0 = supervised
    const bool hiv = lane < 16;            // high state (lane+32) valid

    // ---- sequence length = sum(mask[b, :]) ----
    int len;
    if (MODE == 1) {
        const unsigned int* mrow =
            reinterpret_cast<const unsigned int*>((const unsigned char*)maskv + (size_t)b * TT);
        int cnt = 0;
#pragma unroll
        for (int k2 = 0; k2 < 8; k2++) {
            unsigned int u = mrow[lane + k2 * 32];
            cnt = __dp4a((int)u, 0x01010101, cnt);
        }
#pragma unroll
        for (int o = 16; o > 0; o >>= 1) cnt += __shfl_xor_sync(0xffffffffu, cnt, o);
        len = cnt;
    } else {
        const unsigned int* mrow = (const unsigned int*)maskv + (size_t)b * TT;
        int cnt = 0;
#pragma unroll
        for (int k2 = 0; k2 < 32; k2++) cnt += (mrow[lane + k2 * 32] != 0u) ? 1 : 0;
#pragma unroll
        for (int o = 16; o > 0; o >>= 1) cnt += __shfl_xor_sync(0xffffffffu, cnt, o);
        len = cnt;
    }

    // ---- bool accessors ----
    const unsigned char* tg8 = (const unsigned char*)targetv + (MODE ? (size_t)b * TT * KK : 0);
    const unsigned int* tg32 = (const unsigned int*)targetv + (MODE ? 0 : (size_t)b * TT * KK);
    const unsigned char* sf8 = (const unsigned char*)sforbv;
    const unsigned int* sf32 = (const unsigned int*)sforbv;
    const unsigned char* ef8 = (const unsigned char*)eforbv;
    const unsigned int* ef32 = (const unsigned int*)eforbv;
#define TGT(off) (MODE ? (tg8[off] != 0) : (tg32[off] != 0u))
#define SFB(s)   (MODE ? (sf8[s] != 0) : (sf32[s] != 0u))
#define EFB(s)   (MODE ? (ef8[s] != 0) : (ef32[s] != 0u))

    // ---- load this lane's 2 columns of E (packed) ----
    unsigned long long e[KK];
    const unsigned long long* ep =
        reinterpret_cast<const unsigned long long*>(d_Epacked) + (size_t)lane * KK;
#pragma unroll
    for (int i = 0; i < KK; i++) e[i] = ep[i];

    const float* emb = emissions + (size_t)b * TT * KK;

    // ---- state at t=0: (tier k, residual r) per column ----
    int k0v, k1v;
    float r0v, r1v;
    {
        float em_lo = emb[lane];
        bool m_lo = sup && !TGT(lane);
        bool sf_lo = SFB(lane);
        k0v = (m_lo ? 1 : 0) + (sf_lo ? 1 : 0);
        r0v = (m_lo ? 0.0f : em_lo) + (sf_lo ? 0.0f : startp[lane]);
        if (hiv) {
            float em_hi = emb[32 + lane];
            bool m_hi = sup && !TGT(32 + lane);
            bool sf_hi = SFB(32 + lane);
            k1v = (m_hi ? 1 : 0) + (sf_hi ? 1 : 0);
            r1v = (m_hi ? 0.0f : em_hi) + (sf_hi ? 0.0f : startp[32 + lane]);
        } else {
            k1v = KBIG;
            r1v = NEG_BIG;
        }
    }

    // ---- prefetch row t=1 ----
    float nlo = 0.f, nhi = 0.f;
    bool ntl = true, nth = true;
    {
        const float* er = emb + KK;
        nlo = er[lane];
        nhi = hiv ? er[32 + lane] : 0.0f;
        if (sup) {
            ntl = TGT((size_t)KK + lane);
            nth = hiv ? TGT((size_t)KK + 32 + lane) : true;
        }
    }

    int buf = 0;
    for (int t = 1; t < len; ++t) {
        float cur_lo = nlo, cur_hi = nhi;
        bool msk_lo = sup && !ntl;
        bool msk_hi = sup && !nth;

        // ---- warp reduce: (mk = min tier, mr0 = max r @ mk, mr1 = max r @ mk+1) ----
        int mk;
        float mr0, mr1;
        if (k0v == k1v) { mk = k0v; mr0 = fmaxf(r0v, r1v); mr1 = NEG_BIG; }
        else if (k0v < k1v) { mk = k0v; mr0 = r0v; mr1 = (k1v == k0v + 1) ? r1v : NEG_BIG; }
        else { mk = k1v; mr0 = r1v; mr1 = (k0v == k1v + 1) ? r0v : NEG_BIG; }
#pragma unroll
        for (int o = 16; o > 0; o >>= 1) {
            int ok = __shfl_xor_sync(0xffffffffu, mk, o);
            float o0 = __shfl_xor_sync(0xffffffffu, mr0, o);
            float o1 = __shfl_xor_sync(0xffffffffu, mr1, o);
            if (ok == mk) { mr0 = fmaxf(mr0, o0); mr1 = fmaxf(mr1, o1); }
            else if (ok == mk - 1) { mk = ok; mr1 = fmaxf(o1, mr0); mr0 = o0; }
            else if (ok < mk - 1) { mk = ok; mr0 = o0; mr1 = o1; }
            else if (ok == mk + 1) { mr1 = fmaxf(mr1, o0); }
        }
        const bool has1 = mr1 > NEG_BIG;

        // ---- p0 / p1, store to smem ----
        float p0lo = (k0v == mk) ? __expf(r0v - mr0) : 0.0f;
        float p0hi = (k1v == mk) ? __expf(r1v - mr0) : 0.0f;
        float* pb0 = &psm0[buf][0];
        pb0[lane] = p0lo;
        pb0[32 + lane] = p0hi;
        if (has1) {
            float p1lo = (k0v == mk + 1) ? __expf(r0v - mr1) : 0.0f;
            float p1hi = (k1v == mk + 1) ? __expf(r1v - mr1) : 0.0f;
            float* pb1 = &psm1[buf][0];
            pb1[lane] = p1lo;
            pb1[32 + lane] = p1hi;
        }
        __syncwarp();

        // ---- prefetch next row (overlaps matvec) ----
        int tn = (t + 1 < len) ? (t + 1) : t;
        {
            const float* er = emb + (size_t)tn * KK;
            nlo = er[lane];
            nhi = hiv ? er[32 + lane] : 0.0f;
            if (sup) {
                ntl = TGT((size_t)tn * KK + lane);
                nth = hiv ? TGT((size_t)tn * KK + 32 + lane) : true;
            }
        }

        // ---- matvec A = E^T p0 (and B = E^T p1 if two tiers) ----
        unsigned long long A0 = 0ull, A1 = 0ull, A2 = 0ull, A3 = 0ull;
        {
            const float4* p4 = reinterpret_cast<const float4*>(&psm0[buf][0]);
#pragma unroll
            for (int i = 0; i < KK; i += 4) {
                float4 pv = p4[i >> 2];
                A0 = ffma2(dup2(pv.x), e[i + 0], A0);
                A1 = ffma2(dup2(pv.y), e[i + 1], A1);
                A2 = ffma2(dup2(pv.z), e[i + 2], A2);
                A3 = ffma2(dup2(pv.w), e[i + 3], A3);
            }
        }
        A0 = fadd2(fadd2(A0, A1), fadd2(A2, A3));
        unsigned long long Bc = 0ull;
        if (has1) {
            unsigned long long B0 = 0ull, B1r = 0ull, B2 = 0ull, B3 = 0ull;
            const float4* p4 = reinterpret_cast<const float4*>(&psm1[buf][0]);
#pragma unroll
            for (int i = 0; i < KK; i += 4) {
                float4 pv = p4[i >> 2];
                B0 = ffma2(dup2(pv.x), e[i + 0], B0);
                B1r = ffma2(dup2(pv.y), e[i + 1], B1r);
                B2 = ffma2(dup2(pv.z), e[i + 2], B2);
                B3 = ffma2(dup2(pv.w), e[i + 3], B3);
            }
            Bc = fadd2(fadd2(B0, B1r), fadd2(B2, B3));
        }

        // ---- P0sum (tier-0 mass; forbidden edges carry it to tier+1) ----
        float ps = p0lo + p0hi;
#pragma unroll
        for (int o = 16; o > 0; o >>= 1) ps += __shfl_xor_sync(0xffffffffu, ps, o);

        float Alo, Ahi, Blo, Bhi;
        unpack2(A0, Alo, Ahi);
        unpack2(Bc, Blo, Bhi);

        const float M = has1 ? fmaxf(mr0, mr1) : mr0;
        const float c1 = has1 ? __expf(mr1 - M) : 0.0f;
        const float k0fac = ps * __expf(mr0 - M);

        // ---- column finish ----
        int nk0, nk1 = KBIG;
        float nr0, nr1 = NEG_BIG;
        if (Alo != 0.0f) { nk0 = mk; nr0 = mr0 + __logf(Alo); }
        else { nk0 = mk + 1; nr0 = M + __logf(fmaf(Blo, c1, k0fac)); }
        if (msk_lo) nk0 += 1; else nr0 += cur_lo;
        if (hiv) {
            if (Ahi != 0.0f) { nk1 = mk; nr1 = mr0 + __logf(Ahi); }
            else { nk1 = mk + 1; nr1 = M + __logf(fmaf(Bhi, c1, k0fac)); }
            if (msk_hi) nk1 += 1; else nr1 += cur_hi;
        }
        k0v = nk0; r0v = nr0;
        k1v = nk1; r1v = nr1;
        buf ^= 1;
    }

    // ---- final: z = tiered logsumexp(alpha + end_eff) ----
    {
        bool ef_lo = EFB(lane);
        int zk0 = k0v + (ef_lo ? 1 : 0);
        float zr0 = r0v + (ef_lo ? 0.0f : endp[lane]);
        int zk1 = KBIG;
        float zr1 = NEG_BIG;
        if (hiv) {
            bool ef_hi = EFB(32 + lane);
            zk1 = k1v + (ef_hi ? 1 : 0);
            zr1 = r1v + (ef_hi ? 0.0f : endp[32 + lane]);
        }
        int fk;
        float fr;
        if (zk0 < zk1) { fk = zk0; fr = zr0; }
        else if (zk1 < zk0) { fk = zk1; fr = zr1; }
        else { fk = zk0; fr = fmaxf(zr0, zr1); }
#pragma unroll
        for (int o = 16; o > 0; o >>= 1) {
            int ok = __shfl_xor_sync(0xffffffffu, fk, o);
            float orr = __shfl_xor_sync(0xffffffffu, fr, o);
            if (ok < fk) { fk = ok; fr = orr; }
            else if (ok == fk) { fr = fmaxf(fr, orr); }
        }
        float ss = ((zk0 == fk) ? __expf(zr0 - fr) : 0.0f) +
                   ((zk1 == fk) ? __expf(zr1 - fr) : 0.0f);
#pragma unroll
        for (int o = 16; o > 0; o >>= 1) ss += __shfl_xor_sync(0xffffffffu, ss, o);
        if (lane == 0)
            d_ztmp[chain] = -1.0e7 * (double)fk + (double)(fr + __logf(ss));
    }
#undef TGT
#undef SFB
#undef EFB
}

// ---------------- kernel 3: combine channels ----------------
__global__ void combine_kernel(float* __restrict__ out) {
    int i = blockIdx.x * blockDim.x + threadIdx.x;
    if (i < BB) out[i] = (float)(d_ztmp[2 * i + 1] - d_ztmp[2 * i]);  // unsup - sup
}

extern "C" void kernel_launch(void* const* d_in, const int* in_sizes, int n_in,
                              void* d_out, int out_size) {
    const float* emissions = (const float*)d_in[0];
    const void* mask       = d_in[1];
    const void* target     = d_in[2];
    const float* trans     = (const float*)d_in[3];
    const float* start_t   = (const float*)d_in[4];
    const float* end_t     = (const float*)d_in[5];
    const void* forb       = d_in[6];
    const void* sforb      = d_in[7];
    const void* eforb      = d_in[8];

    detect_kernel<<<1, 32>>>((const unsigned int*)mask);
    precompute_kernel<<<2, 512>>>(trans, forb);
    crf_forward_kernel<1><<<2 * BB, 32>>>(emissions, mask, target, start_t, sforb, end_t, eforb);
    crf_forward_kernel<0><<<2 * BB, 32>>>(emissions, mask, target, start_t, sforb, end_t, eforb);
    combine_kernel<<<2, 256>>>((float*)d_out);
}

// round 4
// speedup vs baseline: 1.7514x; 1.7514x over previous
#include <cuda_runtime.h>

#define KK 48
#define TT 1024
#define BB 512
#define KBIG (1 << 20)
#define NEG_BIG (-3.0e38f)

// ---------------- device scratch ----------------
// d_Epk[(lane*2+c)*24 + k] = (E[2k][j], E[2k+1][j]), j = lane + 32*c
// (zeros for j >= 48). E = exp(trans) or 0 if forbidden.
__device__ float2 d_Epk[64 * 24];
__device__ int d_mode;  // 1 = bools are bytes, 0 = bools are 4-byte words

typedef unsigned long long ull;

__device__ __forceinline__ ull ffma2(ull a, ull b, ull c) {
    ull d;
    asm("fma.rn.f32x2 %0, %1, %2, %3;" : "=l"(d) : "l"(a), "l"(b), "l"(c));
    return d;
}
__device__ __forceinline__ ull fadd2(ull a, ull b) {
    ull d;
    asm("add.rn.f32x2 %0, %1, %2;" : "=l"(d) : "l"(a), "l"(b));
    return d;
}
__device__ __forceinline__ float hsum2(ull v) {
    float lo, hi;
    asm("mov.b64 {%0, %1}, %2;" : "=f"(lo), "=f"(hi) : "l"(v));
    return lo + hi;
}

// ---------------- kernel 1: detect mode + precompute E (single block) ----------------
__global__ void precompute_kernel(const float* __restrict__ trans,
                                  const void* __restrict__ forb,
                                  const unsigned int* __restrict__ maskw) {
    __shared__ int smode;
    int tid = threadIdx.x;
    if (tid == 0) {
        int m = (maskw[0] == 0x01010101u) ? 1 : 0;  // bytes vs words
        smode = m;
        d_mode = m;
    }
    __syncthreads();
    const int mode = smode;
    const unsigned char* f8 = (const unsigned char*)forb;
    const unsigned int* f32v = (const unsigned int*)forb;
    for (int x = tid; x < 64 * 24; x += blockDim.x) {
        int k = x % 24;
        int lc = x / 24;
        int c = lc & 1;
        int l = lc >> 1;
        int j = l + 32 * c;
        float ex = 0.0f, ey = 0.0f;
        if (j < KK) {
            int i0 = 2 * k, i1 = 2 * k + 1;
            bool fb0 = mode ? (f8[i0 * KK + j] != 0) : (f32v[i0 * KK + j] != 0u);
            bool fb1 = mode ? (f8[i1 * KK + j] != 0) : (f32v[i1 * KK + j] != 0u);
            ex = fb0 ? 0.0f : __expf(trans[i0 * KK + j]);
            ey = fb1 ? 0.0f : __expf(trans[i1 * KK + j]);
        }
        d_Epk[x] = make_float2(ex, ey);
    }
}

// ---------------- kernel 2: forward; CTA = 64 thr = {sup warp, unsup warp} of batch b ----------------
template <int MODE>
__global__ void __launch_bounds__(64) crf_forward_kernel(
    const float* __restrict__ emissions,
    const void* __restrict__ maskv,
    const void* __restrict__ targetv,
    const float* __restrict__ startp,
    const void* __restrict__ sforbv,
    const float* __restrict__ endp,
    const void* __restrict__ eforbv,
    float* __restrict__ out) {
    if (d_mode != MODE) return;

    __shared__ __align__(16) float psm[2][2][64];  // [warp][buf][state]
    __shared__ int zk[2];
    __shared__ float zr[2];

    const int tid = threadIdx.x;
    const int w = tid >> 5;
    const int lane = tid & 31;
    const int b = blockIdx.x;
    const bool sup = (w == 0);
    const bool hiv = lane < 16;
    const unsigned FULL = 0xffffffffu;

    // ---- sequence length ----
    int len;
    if (MODE == 1) {
        const unsigned int* mrow =
            reinterpret_cast<const unsigned int*>((const unsigned char*)maskv + (size_t)b * TT);
        int cnt = 0;
#pragma unroll
        for (int k2 = 0; k2 < 8; k2++)
            cnt = __dp4a((int)mrow[lane + k2 * 32], 0x01010101, cnt);
#pragma unroll
        for (int o = 16; o > 0; o >>= 1) cnt += __shfl_xor_sync(FULL, cnt, o);
        len = cnt;
    } else {
        const unsigned int* mrow = (const unsigned int*)maskv + (size_t)b * TT;
        int cnt = 0;
#pragma unroll
        for (int k2 = 0; k2 < 32; k2++) cnt += (mrow[lane + k2 * 32] != 0u) ? 1 : 0;
#pragma unroll
        for (int o = 16; o > 0; o >>= 1) cnt += __shfl_xor_sync(FULL, cnt, o);
        len = cnt;
    }

    // ---- bool accessors ----
    const unsigned char* tg8 = (const unsigned char*)targetv + (MODE ? (size_t)b * TT * KK : 0);
    const unsigned int* tg32 = (const unsigned int*)targetv + (MODE ? 0 : (size_t)b * TT * KK);
    const unsigned char* sf8 = (const unsigned char*)sforbv;
    const unsigned int* sf32 = (const unsigned int*)sforbv;
    const unsigned char* ef8 = (const unsigned char*)eforbv;
    const unsigned int* ef32 = (const unsigned int*)eforbv;
#define TGT(off) (MODE ? (tg8[off] != 0) : (tg32[off] != 0u))
#define SFB(s)   (MODE ? (sf8[s] != 0) : (sf32[s] != 0u))
#define EFB(s)   (MODE ? (ef8[s] != 0) : (ef32[s] != 0u))

    // ---- this lane's E columns, source-pair packed (no MOVs in matvec) ----
    ull e0[24], e1[24];
    {
        const ull* ep = reinterpret_cast<const ull*>(d_Epk) + (size_t)(lane * 2) * 24;
#pragma unroll
        for (int k = 0; k < 24; k++) { e0[k] = ep[k]; e1[k] = ep[24 + k]; }
    }

    const float* emb = emissions + (size_t)b * TT * KK;

    // ---- t=0 state: tier delta (rel. to mk=0) + residual ----
    int mk = 0;
    int dlo, dhi;
    float r0v, r1v;
    {
        bool m_lo = sup && !TGT(lane);
        bool sf_lo = SFB(lane);
        dlo = (m_lo ? 1 : 0) + (sf_lo ? 1 : 0);
        r0v = (m_lo ? 0.0f : emb[lane]) + (sf_lo ? 0.0f : startp[lane]);
        if (hiv) {
            bool m_hi = sup && !TGT(32 + lane);
            bool sf_hi = SFB(32 + lane);
            dhi = (m_hi ? 1 : 0) + (sf_hi ? 1 : 0);
            r1v = (m_hi ? 0.0f : emb[32 + lane]) + (sf_hi ? 0.0f : startp[32 + lane]);
        } else {
            dhi = KBIG;
            r1v = NEG_BIG;
        }
    }
    float anc = 0.0f;

    // ---- prefetch row t=1 ----
    float nlo, nhi;
    bool ntl = true, nth = true;
    {
        nlo = emb[KK + lane];
        nhi = hiv ? emb[KK + 32 + lane] : 0.0f;
        if (sup) {
            ntl = TGT((size_t)KK + lane);
            nth = hiv ? TGT((size_t)KK + 32 + lane) : true;
        }
    }

    int buf = 0;
    for (int t = 1; t < len; ++t) {
        const float cur_lo = nlo, cur_hi = nhi;
        const bool msk_lo = sup && !ntl;
        const bool msk_hi = sup && !nth;

        // ---- min tier via 4 parallel ballots (delta in {0,1,2}) ----
        unsigned blo0 = __ballot_sync(FULL, dlo == 0);
        unsigned bhi0 = __ballot_sync(FULL, hiv && dhi == 0);
        unsigned blo1 = __ballot_sync(FULL, dlo <= 1);
        unsigned bhi1 = __ballot_sync(FULL, hiv && dhi <= 1);
        int m = (blo0 | bhi0) ? 0 : ((blo1 | bhi1) ? 1 : 2);
        mk += m;
        dlo -= m;
        dhi -= m;

        // ---- p = tier-0 mass relative to anchor ----
        float plo = (dlo == 0) ? __expf(r0v - anc) : 0.0f;
        float phi = (hiv && dhi == 0) ? __expf(r1v - anc) : 0.0f;
        float* pb = &psm[w][buf][0];
        pb[lane] = plo;
        pb[32 + lane] = phi;

        // ---- ps reduce (overlaps with matvec below) ----
        float ps = plo + phi;
#pragma unroll
        for (int o = 16; o > 0; o >>= 1) ps += __shfl_xor_sync(FULL, ps, o);

        __syncwarp();

        // ---- prefetch next row ----
        {
            int tn = (t + 1 < len) ? (t + 1) : t;
            const float* er = emb + (size_t)tn * KK;
            nlo = er[lane];
            nhi = hiv ? er[32 + lane] : 0.0f;
            if (sup) {
                ntl = TGT((size_t)tn * KK + lane);
                nth = hiv ? TGT((size_t)tn * KK + 32 + lane) : true;
            }
        }

        // ---- matvec: A_j = sum_i p_i * E[i][j], two columns per lane ----
        ull a0 = 0ull, a1 = 0ull, c0 = 0ull, c1 = 0ull;
        {
            const ulonglong2* pq = reinterpret_cast<const ulonglong2*>(pb);
#pragma unroll
            for (int k = 0; k < 12; k++) {
                ulonglong2 q = pq[k];  // (p[4k],p[4k+1]) , (p[4k+2],p[4k+3])
                a0 = ffma2(q.x, e0[2 * k], a0);
                c0 = ffma2(q.x, e1[2 * k], c0);
                a1 = ffma2(q.y, e0[2 * k + 1], a1);
                c1 = ffma2(q.y, e1[2 * k + 1], c1);
            }
        }
        const float Alo = hsum2(fadd2(a0, a1));
        const float Ahi = hsum2(fadd2(c0, c1));

        // ---- column finish ----
        const float lps = __logf(ps);
        {
            bool pro = (Alo == 0.0f);
            int nd = pro ? 1 : 0;
            float nr = anc + (pro ? lps : __logf(Alo));
            if (msk_lo) nd += 1; else nr += cur_lo;
            dlo = nd;
            r0v = nr;
        }
        if (hiv) {
            bool pro = (Ahi == 0.0f);
            int nd = pro ? 1 : 0;
            float nr = anc + (pro ? lps : __logf(Ahi));
            if (msk_hi) nd += 1; else nr += cur_hi;
            dhi = nd;
            r1v = nr;
        }
        anc += lps;  // anchor = running tier-0 logsumexp (warp-uniform)
        buf ^= 1;
    }

    // ---- final: tiered logsumexp(alpha + end) ----
    {
        bool eflo = EFB(lane);
        int klo = mk + dlo + (eflo ? 1 : 0);
        float rlo = r0v + (eflo ? 0.0f : endp[lane]);
        int khi = KBIG;
        float rhi = NEG_BIG;
        if (hiv) {
            bool efhi = EFB(32 + lane);
            khi = mk + dhi + (efhi ? 1 : 0);
            rhi = r1v + (efhi ? 0.0f : endp[32 + lane]);
        }
        int fk;
        float fr;
        if (klo < khi) { fk = klo; fr = rlo; }
        else if (khi < klo) { fk = khi; fr = rhi; }
        else { fk = klo; fr = fmaxf(rlo, rhi); }
#pragma unroll
        for (int o = 16; o > 0; o >>= 1) {
            int ok = __shfl_xor_sync(FULL, fk, o);
            float orr = __shfl_xor_sync(FULL, fr, o);
            if (ok < fk) { fk = ok; fr = orr; }
            else if (ok == fk) fr = fmaxf(fr, orr);
        }
        float ss = ((klo == fk) ? __expf(rlo - fr) : 0.0f) +
                   ((khi == fk) ? __expf(rhi - fr) : 0.0f);
#pragma unroll
        for (int o = 16; o > 0; o >>= 1) ss += __shfl_xor_sync(FULL, ss, o);
        if (lane == 0) {
            zk[w] = fk;
            zr[w] = fr + __logf(ss);
        }
    }
    __syncthreads();
    if (tid == 0) {
        // out = z_unsup - z_sup ; z = -1e7*k + r
        double v = -1.0e7 * (double)(zk[1] - zk[0]) + (double)(zr[1] - zr[0]);
        out[b] = (float)v;
    }
#undef TGT
#undef SFB
#undef EFB
}

extern "C" void kernel_launch(void* const* d_in, const int* in_sizes, int n_in,
                              void* d_out, int out_size) {
    const float* emissions = (const float*)d_in[0];
    const void* mask       = d_in[1];
    const void* target     = d_in[2];
    const float* trans     = (const float*)d_in[3];
    const float* start_t   = (const float*)d_in[4];
    const float* end_t     = (const float*)d_in[5];
    const void* forb       = d_in[6];
    const void* sforb      = d_in[7];
    const void* eforb      = d_in[8];

    precompute_kernel<<<1, 512>>>(trans, forb, (const unsigned int*)mask);
    crf_forward_kernel<1><<<BB, 64>>>(emissions, mask, target, start_t, sforb,
                                      end_t, eforb, (float*)d_out);
    crf_forward_kernel<0><<<BB, 64>>>(emissions, mask, target, start_t, sforb,
                                      end_t, eforb, (float*)d_out);
}

// round 5
// speedup vs baseline: 1.7768x; 1.0145x over previous
#include <cuda_runtime.h>

#define KK 48
#define TT 1024
#define BB 512
#define KBIG (1 << 20)
#define NEG_BIG (-3.0e38f)

// ---------------- device scratch ----------------
// d_Epk[(lane*2+c)*24 + k] = (E[2k][j], E[2k+1][j]), j = lane + 32*c
__device__ float2 d_Epk[64 * 24];
__device__ int d_mode;  // 1 = bools are bytes, 0 = bools are 4-byte words

typedef unsigned long long ull;

__device__ __forceinline__ ull ffma2(ull a, ull b, ull c) {
    ull d;
    asm("fma.rn.f32x2 %0, %1, %2, %3;" : "=l"(d) : "l"(a), "l"(b), "l"(c));
    return d;
}
__device__ __forceinline__ ull fadd2(ull a, ull b) {
    ull d;
    asm("add.rn.f32x2 %0, %1, %2;" : "=l"(d) : "l"(a), "l"(b));
    return d;
}
__device__ __forceinline__ float hsum2(ull v) {
    float lo, hi;
    asm("mov.b64 {%0, %1}, %2;" : "=f"(lo), "=f"(hi) : "l"(v));
    return lo + hi;
}

// ---------------- kernel 1: detect mode + precompute E ----------------
__global__ void precompute_kernel(const float* __restrict__ trans,
                                  const void* __restrict__ forb,
                                  const unsigned int* __restrict__ maskw) {
    __shared__ int smode;
    int tid = threadIdx.x;
    if (tid == 0) {
        int m = (maskw[0] == 0x01010101u) ? 1 : 0;
        smode = m;
        d_mode = m;
    }
    __syncthreads();
    const int mode = smode;
    const unsigned char* f8 = (const unsigned char*)forb;
    const unsigned int* f32v = (const unsigned int*)forb;
    for (int x = tid; x < 64 * 24; x += blockDim.x) {
        int k = x % 24;
        int lc = x / 24;
        int c = lc & 1;
        int l = lc >> 1;
        int j = l + 32 * c;
        float ex = 0.0f, ey = 0.0f;
        if (j < KK) {
            int i0 = 2 * k, i1 = 2 * k + 1;
            bool fb0 = mode ? (f8[i0 * KK + j] != 0) : (f32v[i0 * KK + j] != 0u);
            bool fb1 = mode ? (f8[i1 * KK + j] != 0) : (f32v[i1 * KK + j] != 0u);
            ex = fb0 ? 0.0f : __expf(trans[i0 * KK + j]);
            ey = fb1 ? 0.0f : __expf(trans[i1 * KK + j]);
        }
        d_Epk[x] = make_float2(ex, ey);
    }
}

// ---------------- kernel 2: forward; CTA = {sup warp, unsup warp} of batch b ----------------
template <int MODE>
__global__ void __launch_bounds__(64) crf_forward_kernel(
    const float* __restrict__ emissions,
    const void* __restrict__ maskv,
    const void* __restrict__ targetv,
    const float* __restrict__ startp,
    const void* __restrict__ sforbv,
    const float* __restrict__ endp,
    const void* __restrict__ eforbv,
    float* __restrict__ out) {
    if (d_mode != MODE) return;

    __shared__ __align__(16) float psm[2][2][64];
    __shared__ int zk[2];
    __shared__ float zr[2];

    const int tid = threadIdx.x;
    const int w = tid >> 5;
    const int lane = tid & 31;
    const int b = blockIdx.x;
    const bool sup = (w == 0);
    const bool hiv = lane < 16;
    const unsigned FULL = 0xffffffffu;

    // ---- sequence length ----
    int len;
    if (MODE == 1) {
        const unsigned int* mrow =
            reinterpret_cast<const unsigned int*>((const unsigned char*)maskv + (size_t)b * TT);
        int cnt = 0;
#pragma unroll
        for (int k2 = 0; k2 < 8; k2++)
            cnt = __dp4a((int)mrow[lane + k2 * 32], 0x01010101, cnt);
#pragma unroll
        for (int o = 16; o > 0; o >>= 1) cnt += __shfl_xor_sync(FULL, cnt, o);
        len = cnt;
    } else {
        const unsigned int* mrow = (const unsigned int*)maskv + (size_t)b * TT;
        int cnt = 0;
#pragma unroll
        for (int k2 = 0; k2 < 32; k2++) cnt += (mrow[lane + k2 * 32] != 0u) ? 1 : 0;
#pragma unroll
        for (int o = 16; o > 0; o >>= 1) cnt += __shfl_xor_sync(FULL, cnt, o);
        len = cnt;
    }
    const int stop = len - 1;  // last step index (len >= 512)

    // ---- bool accessors ----
    const unsigned char* tg8 = (const unsigned char*)targetv + (MODE ? (size_t)b * TT * KK : 0);
    const unsigned int* tg32 = (const unsigned int*)targetv + (MODE ? 0 : (size_t)b * TT * KK);
    const unsigned char* sf8 = (const unsigned char*)sforbv;
    const unsigned int* sf32 = (const unsigned int*)sforbv;
    const unsigned char* ef8 = (const unsigned char*)eforbv;
    const unsigned int* ef32 = (const unsigned int*)eforbv;
#define TGT(off) (MODE ? (tg8[off] != 0) : (tg32[off] != 0u))
#define SFB(s)   (MODE ? (sf8[s] != 0) : (sf32[s] != 0u))
#define EFB(s)   (MODE ? (ef8[s] != 0) : (ef32[s] != 0u))

    // ---- E columns, source-pair packed ----
    ull e0[24], e1[24];
    {
        const ull* ep = reinterpret_cast<const ull*>(d_Epk) + (size_t)(lane * 2) * 24;
#pragma unroll
        for (int k = 0; k < 24; k++) { e0[k] = ep[k]; e1[k] = ep[24 + k]; }
    }

    const float* emb = emissions + (size_t)b * TT * KK;

    // ---- t=0 state ----
    int mk = 0;
    int dlo, dhi;
    float r0v, r1v;
    {
        bool m_lo = sup && !TGT(lane);
        bool sf_lo = SFB(lane);
        dlo = (m_lo ? 1 : 0) + (sf_lo ? 1 : 0);
        r0v = (m_lo ? 0.0f : emb[lane]) + (sf_lo ? 0.0f : startp[lane]);
        if (hiv) {
            bool m_hi = sup && !TGT(32 + lane);
            bool sf_hi = SFB(32 + lane);
            dhi = (m_hi ? 1 : 0) + (sf_hi ? 1 : 0);
            r1v = (m_hi ? 0.0f : emb[32 + lane]) + (sf_hi ? 0.0f : startp[32 + lane]);
        } else {
            dhi = KBIG;
            r1v = NEG_BIG;
        }
    }
    float anc = 0.0f;
    float lps_prev = 0.0f;
    int buf = 0;

    // ---- prefetch ring: rows 1,2,3 -> slots 0,1,2 ----
    float s0lo, s0hi, s1lo, s1hi, s2lo, s2hi;
    bool s0tl = true, s0th = true, s1tl = true, s1th = true, s2tl = true, s2th = true;
#define PRELOAD(SLO, SHI, STL, STH, ROW)                                       \
    {                                                                          \
        const float* er = emb + (size_t)(ROW)*KK;                              \
        SLO = er[lane];                                                        \
        SHI = hiv ? er[32 + lane] : 0.0f;                                      \
        if (sup) {                                                             \
            STL = TGT((size_t)(ROW)*KK + lane);                                \
            STH = hiv ? TGT((size_t)(ROW)*KK + 32 + lane) : true;              \
        }                                                                      \
    }
    PRELOAD(s0lo, s0hi, s0tl, s0th, 1)
    PRELOAD(s1lo, s1hi, s1tl, s1th, 2)
    PRELOAD(s2lo, s2hi, s2tl, s2th, 3)

#define STEP(SLO, SHI, STL, STH, T)                                            \
    do {                                                                       \
        const float cur_lo = SLO, cur_hi = SHI;                                \
        const bool msk_lo = sup && !STL;                                       \
        const bool msk_hi = sup && !STH;                                       \
        {                                                                      \
            int tn = (T) + 3;                                                  \
            if (tn > stop) tn = stop;                                          \
            PRELOAD(SLO, SHI, STL, STH, tn)                                    \
        }                                                                      \
        float ex_lo = __expf(r0v - anc);                                       \
        float ex_hi = __expf(r1v - anc);                                       \
        unsigned any0 = __ballot_sync(FULL, (dlo == 0) || (hiv && dhi == 0));  \
        unsigned any1 = __ballot_sync(FULL, (dlo == 1) || (hiv && dhi == 1));  \
        int m = any0 ? 0 : (any1 ? 1 : 2);                                     \
        mk += m;                                                               \
        float plo = (dlo == m) ? ex_lo : 0.0f;                                 \
        float phi = (hiv && (dhi == m)) ? ex_hi : 0.0f;                        \
        float* pb = &psm[w][buf][0];                                           \
        pb[lane] = plo;                                                        \
        pb[32 + lane] = phi;                                                   \
        __syncwarp();                                                          \
        float ps = plo + phi;                                                  \
        _Pragma("unroll") for (int o = 16; o > 0; o >>= 1)                     \
            ps += __shfl_xor_sync(FULL, ps, o);                                \
        ull a0 = 0, a1 = 0, a2 = 0, a3 = 0, c0 = 0, c1 = 0, c2 = 0, c3 = 0;    \
        {                                                                      \
            const ulonglong2* pq = (const ulonglong2*)pb;                      \
            _Pragma("unroll") for (int k = 0; k < 12; k += 2) {                \
                ulonglong2 qa = pq[k];                                         \
                ulonglong2 qb = pq[k + 1];                                     \
                a0 = ffma2(qa.x, e0[2 * k], a0);                               \
                c0 = ffma2(qa.x, e1[2 * k], c0);                               \
                a1 = ffma2(qa.y, e0[2 * k + 1], a1);                           \
                c1 = ffma2(qa.y, e1[2 * k + 1], c1);                           \
                a2 = ffma2(qb.x, e0[2 * k + 2], a2);                           \
                c2 = ffma2(qb.x, e1[2 * k + 2], c2);                           \
                a3 = ffma2(qb.y, e0[2 * k + 3], a3);                           \
                c3 = ffma2(qb.y, e1[2 * k + 3], c3);                           \
            }                                                                  \
        }                                                                      \
        float Alo = hsum2(fadd2(fadd2(a0, a1), fadd2(a2, a3)));                \
        float Ahi = hsum2(fadd2(fadd2(c0, c1), fadd2(c2, c3)));                \
        float lps_new = __logf(ps);                                            \
        {                                                                      \
            bool pro = !(Alo > 0.0f);                                          \
            float nr = anc + (pro ? lps_prev : __logf(Alo));                   \
            dlo = (pro ? 1 : 0) + (msk_lo ? 1 : 0);                            \
            r0v = msk_lo ? nr : nr + cur_lo;                                   \
        }                                                                      \
        if (hiv) {                                                             \
            bool pro = !(Ahi > 0.0f);                                          \
            float nr = anc + (pro ? lps_prev : __logf(Ahi));                   \
            dhi = (pro ? 1 : 0) + (msk_hi ? 1 : 0);                            \
            r1v = msk_hi ? nr : nr + cur_hi;                                   \
        }                                                                      \
        anc += lps_prev;                                                       \
        lps_prev = lps_new;                                                    \
        buf ^= 1;                                                              \
    } while (0)

    int t = 1;
    for (; t + 2 <= stop; t += 3) {
        STEP(s0lo, s0hi, s0tl, s0th, t);
        STEP(s1lo, s1hi, s1tl, s1th, t + 1);
        STEP(s2lo, s2hi, s2tl, s2th, t + 2);
    }
    if (t <= stop) { STEP(s0lo, s0hi, s0tl, s0th, t); t++; }
    if (t <= stop) { STEP(s1lo, s1hi, s1tl, s1th, t); }

    // ---- final: tiered logsumexp(alpha + end) ----
    {
        bool eflo = EFB(lane);
        int klo = mk + dlo + (eflo ? 1 : 0);
        float rlo = r0v + (eflo ? 0.0f : endp[lane]);
        int khi = KBIG;
        float rhi = NEG_BIG;
        if (hiv) {
            bool efhi = EFB(32 + lane);
            khi = mk + dhi + (efhi ? 1 : 0);
            rhi = r1v + (efhi ? 0.0f : endp[32 + lane]);
        }
        int fk;
        float fr;
        if (klo < khi) { fk = klo; fr = rlo; }
        else if (khi < klo) { fk = khi; fr = rhi; }
        else { fk = klo; fr = fmaxf(rlo, rhi); }
#pragma unroll
        for (int o = 16; o > 0; o >>= 1) {
            int ok = __shfl_xor_sync(FULL, fk, o);
            float orr = __shfl_xor_sync(FULL, fr, o);
            if (ok < fk) { fk = ok; fr = orr; }
            else if (ok == fk) fr = fmaxf(fr, orr);
        }
        float ss = ((klo == fk) ? __expf(rlo - fr) : 0.0f) +
                   ((khi == fk) ? __expf(rhi - fr) : 0.0f);
#pragma unroll
        for (int o = 16; o > 0; o >>= 1) ss += __shfl_xor_sync(FULL, ss, o);
        if (lane == 0) {
            zk[w] = fk;
            zr[w] = fr + __logf(ss);
        }
    }
    __syncthreads();
    if (tid == 0) {
        double v = -1.0e7 * (double)(zk[1] - zk[0]) + (double)(zr[1] - zr[0]);
        out[b] = (float)v;
    }
#undef TGT
#undef SFB
#undef EFB
#undef STEP
#undef PRELOAD
}

extern "C" void kernel_launch(void* const* d_in, const int* in_sizes, int n_in,
                              void* d_out, int out_size) {
    const float* emissions = (const float*)d_in[0];
    const void* mask       = d_in[1];
    const void* target     = d_in[2];
    const float* trans     = (const float*)d_in[3];
    const float* start_t   = (const float*)d_in[4];
    const float* end_t     = (const float*)d_in[5];
    const void* forb       = d_in[6];
    const void* sforb      = d_in[7];
    const void* eforb      = d_in[8];

    precompute_kernel<<<1, 512>>>(trans, forb, (const unsigned int*)mask);
    crf_forward_kernel<1><<<BB, 64>>>(emissions, mask, target, start_t, sforb,
                                      end_t, eforb, (float*)d_out);
    crf_forward_kernel<0><<<BB, 64>>>(emissions, mask, target, start_t, sforb,
                                      end_t, eforb, (float*)d_out);
}